// round 9
// baseline (speedup 1.0000x reference)
#include <cuda_runtime.h>
#include <cuda_bf16.h>
#include <cstdint>

// APoT(8-bit, n=2, signed) quantizer — analytic lattice decode, bit-trick form.
// See R1 derivation: in u = 1.5*|x_norm| space, levels within an octave form a
// power-of-4 grid in the fractional part g, so floor/ceil/nearest reduce to
// single-LOP bit masks + a couple of FADD/FMNMX. No table, no search.

__device__ __forceinline__ float apot_snap(float x, float inva15, float outscale)
{
    uint32_t sgn = __float_as_uint(x) & 0x80000000u;
    float u = fminf(fabsf(x) * inva15, 1.5f);
    uint32_t ub = __float_as_uint(u);
    float base = __uint_as_float(ub & 0x7F800000u);                  // 2^-m
    float f    = __uint_as_float((ub & 0x007FFFFFu) | 0x3F800000u);  // [1,2)
    float g    = f - 1.0f;                                           // [0,1)
    float lo   = __uint_as_float(__float_as_uint(g) & 0x7F000000u);  // pow4 floor
    float up   = fminf(4.0f * lo, 1.0f);                             // pow4 ceil
    float sg   = ((g - lo) > (up - g)) ? up : lo;                    // tie -> lo
    float res  = fmaf(base, sg, base);
    return __uint_as_float(__float_as_uint(res * outscale) | sgn);
}

__device__ __forceinline__ float4 snap4(float4 v, float inva15, float outscale)
{
    float4 r;
    r.x = apot_snap(v.x, inva15, outscale);
    r.y = apot_snap(v.y, inva15, outscale);
    r.z = apot_snap(v.z, inva15, outscale);
    r.w = apot_snap(v.w, inva15, outscale);
    return r;
}

__global__ void __launch_bounds__(256, 8)
apot_quant_kernel(const float* __restrict__ x,
                  const float* __restrict__ alpha,
                  float* __restrict__ out,
                  int n4, int n)
{
    float a = fabsf(__ldg(alpha)) + 1e-8f;
    float inva15   = 1.5f / a;
    float outscale = a * (1.0f / 1.5f);

    const float4* __restrict__ x4 = (const float4*)x;
    float4*       __restrict__ o4 = (float4*)out;

    int stride = gridDim.x * blockDim.x;
    int tid    = blockIdx.x * blockDim.x + threadIdx.x;

    // Uniform full-iteration count: every thread runs exactly nfull branch-free
    // iterations with 4 independent LDG.128 batched up front (MLP_p1 = 4).
    int nfull = n4 / (4 * stride);
    int i = tid;
    for (int it = 0; it < nfull; ++it, i += 4 * stride) {
        float4 v0 = __ldcs(&x4[i]);
        float4 v1 = __ldcs(&x4[i +     stride]);
        float4 v2 = __ldcs(&x4[i + 2 * stride]);
        float4 v3 = __ldcs(&x4[i + 3 * stride]);
        __stcs(&o4[i],              snap4(v0, inva15, outscale));
        __stcs(&o4[i +     stride], snap4(v1, inva15, outscale));
        __stcs(&o4[i + 2 * stride], snap4(v2, inva15, outscale));
        __stcs(&o4[i + 3 * stride], snap4(v3, inva15, outscale));
    }

    // remainder region (bounds-checked)
    for (; i < n4; i += stride) {
        __stcs(&o4[i], snap4(__ldcs(&x4[i]), inva15, outscale));
    }

    // scalar tail (n not divisible by 4)
    int tail = n & 3;
    if (blockIdx.x == 0 && (int)threadIdx.x < tail) {
        int idx = (n4 << 2) + threadIdx.x;
        out[idx] = apot_snap(x[idx], inva15, outscale);
    }
}

extern "C" void kernel_launch(void* const* d_in, const int* in_sizes, int n_in,
                              void* d_out, int out_size)
{
    const float* x     = (const float*)d_in[0];
    const float* alpha = (const float*)d_in[1];
    // d_in[2] (levels) unused: lattice decoded analytically.
    float* out = (float*)d_out;

    int n  = in_sizes[0];
    int n4 = n >> 2;

    int threads = 256;
    int blocks  = 1184;                       // 148 SMs x 8 blocks = 1 full wave
    int needed  = (n4 + threads - 1) / threads;
    if (needed < 1) needed = 1;
    if (blocks > needed) blocks = needed;

    apot_quant_kernel<<<blocks, threads>>>(x, alpha, out, n4, n);
}

// round 11
// speedup vs baseline: 1.0593x; 1.0593x over previous
#include <cuda_runtime.h>
#include <cuda_bf16.h>
#include <cstdint>

// APoT(8-bit, n=2, signed) quantizer — analytic lattice decode, bit-trick form.
// In u = 1.5*|x_norm| space, levels within an octave form a power-of-4 grid in
// the fractional part g: floor/ceil/nearest reduce to single-LOP bit masks plus
// a few FADD/FMNMX. No table, no search.
//
// Memory shape: MLP_p1 = 2 front-batched LDG.128 per iteration at occ 8
// (oe*MLP_p1 = 16 = L1tex queue soft threshold — measured optimum; *4 batching
// regressed to 75.3% DRAM via cross-CTA queue contention, R5).

__device__ __forceinline__ float apot_snap(float x, float inva15, float outscale)
{
    uint32_t sgn = __float_as_uint(x) & 0x80000000u;
    float u = fminf(fabsf(x) * inva15, 1.5f);
    uint32_t ub = __float_as_uint(u);
    float base = __uint_as_float(ub & 0x7F800000u);                  // 2^-m
    float f    = __uint_as_float((ub & 0x007FFFFFu) | 0x3F800000u);  // [1,2)
    float g    = f - 1.0f;                                           // [0,1)
    float lo   = __uint_as_float(__float_as_uint(g) & 0x7F000000u);  // pow4 floor
    float up   = fminf(4.0f * lo, 1.0f);                             // pow4 ceil
    float sg   = ((g - lo) > (up - g)) ? up : lo;                    // tie -> lo
    float res  = fmaf(base, sg, base);
    return __uint_as_float(__float_as_uint(res * outscale) | sgn);
}

__device__ __forceinline__ float4 snap4(float4 v, float inva15, float outscale)
{
    float4 r;
    r.x = apot_snap(v.x, inva15, outscale);
    r.y = apot_snap(v.y, inva15, outscale);
    r.z = apot_snap(v.z, inva15, outscale);
    r.w = apot_snap(v.w, inva15, outscale);
    return r;
}

__global__ void __launch_bounds__(256, 8)
apot_quant_kernel(const float* __restrict__ x,
                  const float* __restrict__ alpha,
                  float* __restrict__ out,
                  int n4, int n)
{
    float a = fabsf(__ldg(alpha)) + 1e-8f;
    float inva15   = 1.5f / a;
    float outscale = a * (1.0f / 1.5f);

    const float4* __restrict__ x4 = (const float4*)x;
    float4*       __restrict__ o4 = (float4*)out;

    int stride = gridDim.x * blockDim.x;
    int tid    = blockIdx.x * blockDim.x + threadIdx.x;

    // Branch-free main loop: exactly nfull iterations for every thread,
    // 2 independent LDG.128 batched up front (MLP_p1 = 2).
    int nfull = n4 / (2 * stride);
    int i = tid;
    for (int it = 0; it < nfull; ++it, i += 2 * stride) {
        float4 v0 = __ldcs(&x4[i]);
        float4 v1 = __ldcs(&x4[i + stride]);
        __stcs(&o4[i],          snap4(v0, inva15, outscale));
        __stcs(&o4[i + stride], snap4(v1, inva15, outscale));
    }

    // remainder region (bounds-checked)
    for (; i < n4; i += stride) {
        __stcs(&o4[i], snap4(__ldcs(&x4[i]), inva15, outscale));
    }

    // scalar tail (n not divisible by 4)
    int tail = n & 3;
    if (blockIdx.x == 0 && (int)threadIdx.x < tail) {
        int idx = (n4 << 2) + threadIdx.x;
        out[idx] = apot_snap(x[idx], inva15, outscale);
    }
}

extern "C" void kernel_launch(void* const* d_in, const int* in_sizes, int n_in,
                              void* d_out, int out_size)
{
    const float* x     = (const float*)d_in[0];
    const float* alpha = (const float*)d_in[1];
    // d_in[2] (levels) unused: lattice decoded analytically.
    float* out = (float*)d_out;

    int n  = in_sizes[0];
    int n4 = n >> 2;

    int threads = 256;
    int blocks  = 1184;                       // 148 SMs x 8 blocks = 1 full wave
    int needed  = (n4 + threads - 1) / threads;
    if (needed < 1) needed = 1;
    if (blocks > needed) blocks = needed;

    apot_quant_kernel<<<blocks, threads>>>(x, alpha, out, n4, n);
}